// round 3
// baseline (speedup 1.0000x reference)
#include <cuda_runtime.h>

// QuadraticProjectionLoss
//   B=8192, V=8, J=32
//   inputs (metadata order): K [B,V,3,3] f32, cam_preds [B,V,3,4] f32,
//                            kps_world_pred [B,J,3] f32, initial_keypoints [B,V,J,2] f32
//   output: scalar f32 (mean over B,V of per_view_loss * penal)

#define BB 8192
#define VV 8
#define JJ 32
#define NBLK BB                      // one block per batch
#define THRESH 100.0f
#define POW_C 63.095734448019324f    // 100^0.9

__device__ float g_partials[NBLK];

__global__ __launch_bounds__(256) void qpl_main(
    const float* __restrict__ K_g,
    const float* __restrict__ cam_g,
    const float* __restrict__ kps_g,
    const float* __restrict__ init_g)
{
    const int b    = blockIdx.x;
    const int wv   = threadIdx.x >> 5;   // view 0..7 (warp id)
    const int lane = threadIdx.x & 31;   // keypoint j 0..31

    // world keypoint (shared across views; L1 broadcast within block)
    const float* kp = kps_g + ((size_t)b * JJ + lane) * 3;
    const float X = kp[0], Y = kp[1], Z = kp[2];

    // camera extrinsics [3x4] — warp-uniform loads
    const float* cm = cam_g + ((size_t)b * VV + wv) * 12;
    const float p0 = cm[0] * X + cm[1] * Y + cm[2]  * Z + cm[3];
    const float p1 = cm[4] * X + cm[5] * Y + cm[6]  * Z + cm[7];
    const float p2 = cm[8] * X + cm[9] * Y + cm[10] * Z + cm[11];

    // intrinsics [3x3] — warp-uniform loads
    const float* km = K_g + ((size_t)b * VV + wv) * 9;
    const float i0 = km[0] * p0 + km[1] * p1 + km[2] * p2;
    const float i1 = km[3] * p0 + km[4] * p1 + km[5] * p2;
    const float i2 = km[6] * p0 + km[7] * p1 + km[8] * p2;

    const float inv = __fdividef(1.0f, i2);
    const float px = i0 * inv;
    const float py = i1 * inv;

    // initial keypoints — coalesced float2 stream
    const float2 ik =
        reinterpret_cast<const float2*>(init_g)[((size_t)b * VV + wv) * JJ + lane];

    float s_pn = px * px + py * py;          // sum proj^2   -> ||proj||
    float s_in = ik.x * ik.x + ik.y * ik.y;  // sum init^2   -> ||init||

    // KeypointsMSESmoothLoss on scaled keypoints
    float dx = (px - ik.x) * 0.1f; dx *= dx;
    float dy = (py - ik.y) * 0.1f; dy *= dy;
    if (dx > THRESH) dx = __powf(dx, 0.1f) * POW_C;
    if (dy > THRESH) dy = __powf(dy, 0.1f) * POW_C;
    float s_d = dx + dy;

    // warp reduction over the 32 keypoints (3 values)
    #pragma unroll
    for (int o = 16; o; o >>= 1) {
        s_pn += __shfl_xor_sync(0xffffffffu, s_pn, o);
        s_in += __shfl_xor_sync(0xffffffffu, s_in, o);
        s_d  += __shfl_xor_sync(0xffffffffu, s_d,  o);
    }

    __shared__ float sh[VV];
    if (lane == 0) {
        const float penal = fabsf(sqrtf(s_pn) / sqrtf(s_in) - 1.0f);
        sh[wv] = 0.5f * s_d * penal;         // per_view_loss * penal
    }
    __syncthreads();
    if (threadIdx.x == 0) {
        float t = 0.0f;
        #pragma unroll
        for (int i = 0; i < VV; i++) t += sh[i];
        g_partials[b] = t;
    }
}

__global__ __launch_bounds__(256) void qpl_reduce(float* __restrict__ out)
{
    double acc = 0.0;
    for (int i = threadIdx.x; i < NBLK; i += 256)
        acc += (double)g_partials[i];

    __shared__ double sh[256];
    sh[threadIdx.x] = acc;
    __syncthreads();
    #pragma unroll
    for (int s = 128; s; s >>= 1) {
        if (threadIdx.x < s) sh[threadIdx.x] += sh[threadIdx.x + s];
        __syncthreads();
    }
    if (threadIdx.x == 0)
        out[0] = (float)(sh[0] / (double)(BB * VV));
}

extern "C" void kernel_launch(void* const* d_in, const int* in_sizes, int n_in,
                              void* d_out, int out_size)
{
    const float* K    = (const float*)d_in[0];
    const float* cam  = (const float*)d_in[1];
    const float* kps  = (const float*)d_in[2];
    const float* init = (const float*)d_in[3];

    qpl_main<<<NBLK, 256>>>(K, cam, kps, init);
    qpl_reduce<<<1, 256>>>((float*)d_out);
}

// round 4
// speedup vs baseline: 1.2336x; 1.2336x over previous
#include <cuda_runtime.h>

// QuadraticProjectionLoss — fused single kernel
//   B=8192, V=8, J=32
//   inputs: K [B,V,3,3] f32, cam_preds [B,V,3,4] f32,
//           kps_world_pred [B,J,3] f32, initial_keypoints [B,V,J,2] f32
//   output: scalar f32
//
// Layout: 1024 blocks x 256 threads. warp = one batch b.
//   lane = v*4 + g : view v in 0..7, keypoint-group g in 0..3 (8 kps each).
// Final mean computed by the last block to finish (deterministic fixed-order sum).

#define BB 8192
#define VV 8
#define JJ 32
#define NWARP_BLK 8
#define NBLK (BB / NWARP_BLK)        // 1024
#define THRESH 100.0f
#define POW_C 63.095734448019324f    // 100^0.9

__device__ float    g_partials[BB];
__device__ unsigned g_count = 0;     // self-resetting completion counter

__global__ __launch_bounds__(256) void qpl_fused(
    const float* __restrict__ K_g,
    const float* __restrict__ cam_g,
    const float* __restrict__ kps_g,
    const float* __restrict__ init_g,
    float* __restrict__ out)
{
    const int w    = blockIdx.x * NWARP_BLK + (threadIdx.x >> 5);  // batch b
    const int lane = threadIdx.x & 31;
    const int v    = lane >> 2;        // view 0..7
    const int g    = lane & 3;         // keypoint group 0..3

    // ---- world keypoints: 8 kps = 24 floats, float4 x6 (96B, 16B-aligned) ----
    float kf[24];
    {
        const float4* kp4 = reinterpret_cast<const float4*>(
            kps_g + (size_t)w * (JJ * 3) + g * 24);
        #pragma unroll
        for (int i = 0; i < 6; i++) {
            float4 q = kp4[i];
            kf[4*i+0] = q.x; kf[4*i+1] = q.y; kf[4*i+2] = q.z; kf[4*i+3] = q.w;
        }
    }

    // ---- cam [3x4] as float4 x3 (48B aligned); K [3x3] scalars ----
    float ca[12];
    {
        const float4* c4 = reinterpret_cast<const float4*>(
            cam_g + ((size_t)w * VV + v) * 12);
        #pragma unroll
        for (int i = 0; i < 3; i++) {
            float4 q = c4[i];
            ca[4*i+0] = q.x; ca[4*i+1] = q.y; ca[4*i+2] = q.z; ca[4*i+3] = q.w;
        }
    }
    float kk[9];
    {
        const float* kb = K_g + ((size_t)w * VV + v) * 9;
        #pragma unroll
        for (int i = 0; i < 9; i++) kk[i] = kb[i];
    }

    // ---- fuse: M = K(3x3) @ cam(3x4), one 3x4 matvec per keypoint after ----
    float M[12];
    #pragma unroll
    for (int r = 0; r < 3; r++)
        #pragma unroll
        for (int c = 0; c < 4; c++)
            M[r*4+c] = kk[r*3+0]*ca[0*4+c] + kk[r*3+1]*ca[1*4+c] + kk[r*3+2]*ca[2*4+c];

    // ---- initial keypoints: 8 float2 = float4 x4 (64B, aligned) ----
    float ikf[16];
    {
        const float4* i4 = reinterpret_cast<const float4*>(
            init_g + (((size_t)w * VV + v) * JJ + g * 8) * 2);
        #pragma unroll
        for (int i = 0; i < 4; i++) {
            float4 q = i4[i];
            ikf[4*i+0] = q.x; ikf[4*i+1] = q.y; ikf[4*i+2] = q.z; ikf[4*i+3] = q.w;
        }
    }

    // ---- per-lane accumulation over 8 keypoints ----
    float s_pn = 0.0f, s_in = 0.0f, s_d = 0.0f;
    #pragma unroll
    for (int k = 0; k < 8; k++) {
        const float X = kf[3*k], Y = kf[3*k+1], Z = kf[3*k+2];
        const float i0 = fmaf(M[0], X, fmaf(M[1], Y, fmaf(M[2],  Z, M[3])));
        const float i1 = fmaf(M[4], X, fmaf(M[5], Y, fmaf(M[6],  Z, M[7])));
        const float i2 = fmaf(M[8], X, fmaf(M[9], Y, fmaf(M[10], Z, M[11])));
        const float inv = __fdividef(1.0f, i2);
        const float px = i0 * inv;
        const float py = i1 * inv;
        const float ix = ikf[2*k], iy = ikf[2*k+1];

        s_pn = fmaf(px, px, fmaf(py, py, s_pn));
        s_in = fmaf(ix, ix, fmaf(iy, iy, s_in));

        float dx = (px - ix) * 0.1f; dx *= dx;
        float dy = (py - iy) * 0.1f; dy *= dy;
        if (dx > THRESH) dx = __powf(dx, 0.1f) * POW_C;
        if (dy > THRESH) dy = __powf(dy, 0.1f) * POW_C;
        s_d += dx + dy;
    }

    // ---- reduce within the 4-lane group (same view) ----
    s_pn += __shfl_xor_sync(0xffffffffu, s_pn, 1);
    s_pn += __shfl_xor_sync(0xffffffffu, s_pn, 2);
    s_in += __shfl_xor_sync(0xffffffffu, s_in, 1);
    s_in += __shfl_xor_sync(0xffffffffu, s_in, 2);
    s_d  += __shfl_xor_sync(0xffffffffu, s_d,  1);
    s_d  += __shfl_xor_sync(0xffffffffu, s_d,  2);

    // every lane of a quad now holds the per-view sums; compute view loss
    const float penal = fabsf(sqrtf(s_pn) * __frsqrt_rn(s_in) * rsqrtf(1.0f) - 1.0f);
    float loss = 0.5f * s_d * penal;     // identical within each quad

    // sum the 8 distinct views (quads hold equal values, xor4/8/16 sums quads)
    loss += __shfl_xor_sync(0xffffffffu, loss, 4);
    loss += __shfl_xor_sync(0xffffffffu, loss, 8);
    loss += __shfl_xor_sync(0xffffffffu, loss, 16);

    if (lane == 0) g_partials[w] = loss;

    // ---- last-block-done final reduction (deterministic) ----
    __shared__ bool isLast;
    __threadfence();
    __syncthreads();
    if (threadIdx.x == 0) {
        unsigned old = atomicAdd(&g_count, 1u);
        isLast = (old == (unsigned)(gridDim.x - 1));
    }
    __syncthreads();

    if (isLast) {
        double acc = 0.0;
        for (int i = threadIdx.x; i < BB; i += 256)
            acc += (double)g_partials[i];            // fixed order per thread

        __shared__ double sh[256];
        sh[threadIdx.x] = acc;
        __syncthreads();
        #pragma unroll
        for (int s = 128; s; s >>= 1) {
            if (threadIdx.x < s) sh[threadIdx.x] += sh[threadIdx.x + s];
            __syncthreads();
        }
        if (threadIdx.x == 0) {
            out[0] = (float)(sh[0] / (double)(BB * VV));
            g_count = 0;                             // reset for next graph replay
        }
    }
}

extern "C" void kernel_launch(void* const* d_in, const int* in_sizes, int n_in,
                              void* d_out, int out_size)
{
    const float* K    = (const float*)d_in[0];
    const float* cam  = (const float*)d_in[1];
    const float* kps  = (const float*)d_in[2];
    const float* init = (const float*)d_in[3];

    qpl_fused<<<NBLK, 256>>>(K, cam, kps, init, (float*)d_out);
}